// round 16
// baseline (speedup 1.0000x reference)
#include <cuda_runtime.h>
#include <cuda_fp16.h>
#include <cstdint>
#include <math.h>

// ---------------------------------------------------------------------------
// CompressiveEncoder forward. FP16 mma.sync + ldmatrix(.trans) + cp.async.
// TRB weight GEMMs (no transposes); packed softmax; split-parallel attnsum.
// Output: x | new_mems | new_cmems | aux | 0 | attns_mean  (fp32)
// ---------------------------------------------------------------------------

#define OFF_MEMS   2097152L
#define OFF_CMEMS 10485760L
#define OFF_AUX   12582912L
#define OFF_ZERO  12582913L
#define OFF_ATTN  12582914L
#define ATTN_ELEMS 589824L

// -------------------- device scratch ---------------------------------------
__device__ __half g_hmems [8388608];
__device__ __half g_hcmems[2097152];
__device__ __half g_hxn   [2097152];
__device__ __half g_hxn2  [2097152];
__device__ __half g_qh    [8388608];
__device__ __half g_kvh   [37748736];
__device__ __half g_ckvh  [4194304];
__device__ __half g_dotsH [150994944];
__device__ __half g_dots2H[16777216];
__device__ __half g_attnoh[2097152];
__device__ __half g_ffhh  [8388608];
__device__ __half g_cmh   [2097152];
__device__ __half g_wqkv16[6291456];     // [l][512][1536]: cols 0-511 Wq, 512-1535 Wkv
__device__ __half g_hWo   [1048576];
__device__ __half g_cwh   [4194304];     // conv as B^T [N,K]
__device__ __half g_hW1   [4194304];
__device__ __half g_hW2   [4194304];
__device__ float g_o1 [8388608];
__device__ float g_o2 [8388608];
__device__ float g_S  [131072];

// -------------------- helpers ----------------------------------------------
__device__ __forceinline__ void mma_f16(float* d, uint32_t a0, uint32_t a1,
                                        uint32_t a2, uint32_t a3,
                                        uint32_t b0, uint32_t b1) {
    asm volatile("mma.sync.aligned.m16n8k16.row.col.f32.f16.f16.f32 "
                 "{%0,%1,%2,%3}, {%4,%5,%6,%7}, {%8,%9}, {%0,%1,%2,%3};"
                 : "+f"(d[0]), "+f"(d[1]), "+f"(d[2]), "+f"(d[3])
                 : "r"(a0), "r"(a1), "r"(a2), "r"(a3), "r"(b0), "r"(b1));
}
#define LDSM_X4(r0, r1, r2, r3, addr) \
    asm volatile("ldmatrix.sync.aligned.m8n8.x4.shared.b16 {%0,%1,%2,%3}, [%4];" \
                 : "=r"(r0), "=r"(r1), "=r"(r2), "=r"(r3) : "r"(addr))
#define LDSM_X4_T(r0, r1, r2, r3, addr) \
    asm volatile("ldmatrix.sync.aligned.m8n8.x4.trans.shared.b16 {%0,%1,%2,%3}, [%4];" \
                 : "=r"(r0), "=r"(r1), "=r"(r2), "=r"(r3) : "r"(addr))
#define CP16(saddr, gaddr) \
    asm volatile("cp.async.cg.shared.global [%0], [%1], 16;" :: "r"(saddr), "l"(gaddr))
#define CP_COMMIT() asm volatile("cp.async.commit_group;" ::: "memory")
#define CP_WAIT1()  asm volatile("cp.async.wait_group 1;" ::: "memory")

__device__ __forceinline__ float gelu_f(float v) {
    return 0.5f * v * (1.f + erff(v * 0.70710678118654752f));
}

// -------------------- FP16 GEMM (unchanged) ---------------------------------
template<int BN, int EPI, int OUT, bool TRB, bool AUX>
__global__ void __launch_bounds__(256)
hm_gemm(const __half* __restrict__ A, const __half* __restrict__ B,
        float* __restrict__ Cf, __half* __restrict__ Ch,
        int K, int lda, int ldb, int ldc,
        long sA1, long sA2, long sA3, long sB1, long sB2, long sB3,
        long sC1, long sC2, long sC3, int zm2, int zm3,
        const float* __restrict__ bias, long sBias, long sD1, long sD2)
{
    constexpr int BM = 128, NST = 3;
    constexpr int BNB = BN * 2 + 16;
    constexpr int ABY = BM * 80;
    constexpr int STGB = TRB ? (ABY + 32 * BNB) : ((BM + BN) * 80);
    constexpr int WN = (BN == 128) ? 4 : 2, WM = 8 / WN;
    constexpr int WTM = BM / WM;
    constexpr int MF = WTM / 16;
    constexpr int NBn = (BN == 128) ? 2 : 1;
    constexpr int NBt = (32 * (BN / 8)) / 256;

    extern __shared__ char smc[];
    uint32_t sbase;
    asm("{ .reg .u64 t; cvta.to.shared.u64 t, %1; cvt.u32.u64 %0, t; }"
        : "=r"(sbase) : "l"(smc));

    const int z = blockIdx.z;
    const int z1 = z / (zm2 * zm3);
    const int z2 = (z / zm3) % zm2;
    const int z3 = z % zm3;
    A += z1 * sA1 + z2 * sA2 + z3 * sA3;
    B += z1 * sB1 + z2 * sB2 + z3 * sB3;
    __half* Ch2 = nullptr;
    if (OUT == 3) {
        Ch  += z1 * sC1;
        Ch2 = ((__half*)Cf) + z1 * sC3;
    } else {
        const long coff = z1 * sC1 + z2 * sC2 + z3 * sC3;
        if (OUT != 1) Cf += coff;
        if (OUT >= 1) Ch += coff;
    }
    if (AUX) Cf += z1 * sD1 + z2 * sD2;
    if (EPI >= 1) bias += z1 * sBias;
    const int m0 = blockIdx.y * BM, n0 = blockIdx.x * BN;
    const int tid = threadIdx.x, lane = tid & 31, wid = tid >> 5;
    const int wm = wid % WM, wn = wid / WM;
    const int mbase = wm * WTM, nbase = wn * 32;

    float acc[MF][4][4];
    float acc2[AUX ? MF : 1][4][4];
#pragma unroll
    for (int i = 0; i < MF; i++)
#pragma unroll
        for (int j = 0; j < 4; j++)
#pragma unroll
            for (int r = 0; r < 4; r++) acc[i][j][r] = 0.f;

    const int KT = K >> 5;

    auto issue = [&](int kt, int st) {
        const int k0 = kt << 5;
        const uint32_t s0 = sbase + st * STGB;
#pragma unroll
        for (int i = 0; i < 2; i++) {
            int idx = tid + i * 256, r = idx >> 2, c = idx & 3;
            CP16(s0 + r * 80 + c * 16, A + (long)(m0 + r) * lda + k0 + c * 8);
        }
        if (!TRB) {
#pragma unroll
            for (int i = 0; i < NBn; i++) {
                int idx = tid + i * 256, r = idx >> 2, c = idx & 3;
                CP16(s0 + ABY + r * 80 + c * 16,
                     B + (long)(n0 + r) * ldb + k0 + c * 8);
            }
        } else {
            constexpr int CH = BN / 8;
#pragma unroll
            for (int i = 0; i < NBt; i++) {
                int idx = tid + i * 256, r = idx / CH, c = idx % CH;
                CP16(s0 + ABY + r * BNB + c * 16,
                     B + (long)(k0 + r) * ldb + n0 + c * 8);
            }
        }
    };

    const int g2 = lane >> 3, t7 = lane & 7;
    const uint32_t khalf = ((g2 >> 1) << 4);
    uint32_t aoff[MF], boff[2];
#pragma unroll
    for (int mf = 0; mf < MF; mf++)
        aoff[mf] = (uint32_t)(mbase + mf * 16 + ((g2 & 1) << 3) + t7) * 80 + khalf;
    if (!TRB) {
#pragma unroll
        for (int np = 0; np < 2; np++)
            boff[np] = (uint32_t)ABY +
                       (uint32_t)(nbase + np * 16 + ((g2 & 1) << 3) + t7) * 80 + khalf;
    } else {
#pragma unroll
        for (int np = 0; np < 2; np++)
            boff[np] = (uint32_t)ABY +
                       (uint32_t)(((g2 >> 1) << 3) + t7) * BNB +
                       (uint32_t)(nbase + np * 16 + ((g2 & 1) << 3)) * 2;
    }

    auto compute = [&](int st) {
        const uint32_t s0 = sbase + st * STGB;
#pragma unroll
        for (int ks = 0; ks < 2; ks++) {
            uint32_t a[MF][4], b[2][4];
#pragma unroll
            for (int mf = 0; mf < MF; mf++)
                LDSM_X4(a[mf][0], a[mf][1], a[mf][2], a[mf][3],
                        s0 + aoff[mf] + ks * 32);
#pragma unroll
            for (int np = 0; np < 2; np++) {
                if (!TRB) {
                    LDSM_X4(b[np][0], b[np][1], b[np][2], b[np][3],
                            s0 + boff[np] + ks * 32);
                } else {
                    LDSM_X4_T(b[np][0], b[np][1], b[np][2], b[np][3],
                              s0 + boff[np] + ks * 16 * BNB);
                }
            }
#pragma unroll
            for (int mf = 0; mf < MF; mf++)
#pragma unroll
                for (int np = 0; np < 2; np++) {
                    mma_f16(acc[mf][2 * np],     a[mf][0], a[mf][1], a[mf][2], a[mf][3],
                            b[np][0], b[np][2]);
                    mma_f16(acc[mf][2 * np + 1], a[mf][0], a[mf][1], a[mf][2], a[mf][3],
                            b[np][1], b[np][3]);
                }
        }
    };

    int ldi = 0;
#pragma unroll
    for (int s = 0; s < NST - 1; s++) {
        if (ldi < KT) issue(ldi, s);
        CP_COMMIT();
        ldi++;
    }
    for (int kt = 0; kt < KT; kt++) {
        if (AUX) {
            if (kt == 4) {
#pragma unroll
                for (int i = 0; i < MF; i++)
#pragma unroll
                    for (int j = 0; j < 4; j++)
#pragma unroll
                        for (int r = 0; r < 4; r++) acc2[i][j][r] = acc[i][j][r];
            }
            if (kt == 20) {
#pragma unroll
                for (int i = 0; i < MF; i++)
#pragma unroll
                    for (int j = 0; j < 4; j++)
#pragma unroll
                        for (int r = 0; r < 4; r++)
                            acc2[i][j][r] = acc[i][j][r] - acc2[i][j][r];
            }
        }
        CP_WAIT1();
        __syncthreads();
        compute(kt % NST);
        if (ldi < KT) issue(ldi, ldi % NST);
        CP_COMMIT();
        ldi++;
    }

    const bool qside = (n0 < 512);
    const int rbase = m0 + mbase + (lane >> 2);
    const int cbase = n0 + nbase + 2 * (lane & 3);
#pragma unroll
    for (int mf = 0; mf < MF; mf++) {
#pragma unroll
        for (int nf = 0; nf < 4; nf++) {
#pragma unroll
            for (int half = 0; half < 2; half++) {
                const int m = rbase + mf * 16 + half * 8;
                const int n = cbase + nf * 8;
                float2 v = make_float2(acc[mf][nf][half * 2], acc[mf][nf][half * 2 + 1]);
                if (EPI >= 1) { v.x += bias[n]; v.y += bias[n + 1]; }
                if (OUT == 3) {
                    __half2 h2 = __floats2half2_rn(v.x, v.y);
                    if (qside) *(__half2*)(Ch  + (long)m * 512  + n)        = h2;
                    else       *(__half2*)(Ch2 + (long)m * 1024 + (n - 512)) = h2;
                } else {
                    const long idx = (long)m * ldc + n;
                    if (EPI == 2) { float2 c0 = *(const float2*)(Cf + idx); v.x += c0.x; v.y += c0.y; }
                    if (EPI == 3) { v.x = gelu_f(v.x); v.y = gelu_f(v.y); }
                    if (OUT != 1) *(float2*)(Cf + idx) = v;
                    if (OUT == 1 || OUT == 2) *(__half2*)(Ch + idx) = __floats2half2_rn(v.x, v.y);
                }
                if (AUX) {
                    float2 w = make_float2(acc2[mf][nf][half * 2], acc2[mf][nf][half * 2 + 1]);
                    *(float2*)(Cf + (long)m * 64 + n) = w;
                }
            }
        }
    }
}

// -------------------- conversions ------------------------------------------
__global__ void convt2_k(const float* __restrict__ w, __half* __restrict__ wt)
{
    long i = (long)blockIdx.x * 256 + threadIdx.x;
    if (i >= 4L * 1048576L) return;
    long l = i >> 20, r0 = i & 1048575L;
    int o = (int)(r0 >> 11), k = (int)(r0 & 2047);
    int r = k >> 9, c = k & 511;
    wt[i] = __float2half(w[l * 1048576L + ((long)o * 512 + c) * 4 + r]);
}

__global__ void cvt16_k(const float* __restrict__ in, __half* __restrict__ out, long n4)
{
    long i = (long)blockIdx.x * 256 + threadIdx.x;
    if (i >= n4) return;
    float4 v = ((const float4*)in)[i];
    ((__half2*)out)[2 * i]     = __floats2half2_rn(v.x, v.y);
    ((__half2*)out)[2 * i + 1] = __floats2half2_rn(v.z, v.w);
}

__global__ void cvtpad_k(const float* __restrict__ in, __half* __restrict__ out,
                         int C4, int R, int P, long sOut, long n4)
{
    long i = (long)blockIdx.x * 256 + threadIdx.x;
    if (i >= n4) return;
    long per = (long)R * C4;
    long l = i / per, rem = i - l * per;
    int row = (int)(rem / C4), c4 = (int)(rem - (long)row * C4);
    float4 v = ((const float4*)in)[i];
    __half2* o = (__half2*)(out + l * sOut + (long)row * P + c4 * 4);
    o[0] = __floats2half2_rn(v.x, v.y);
    o[1] = __floats2half2_rn(v.z, v.w);
}

// -------------------- layernorm (float4) ------------------------------------
__global__ void ln_k(const float* __restrict__ x, const float* __restrict__ g,
                     const float* __restrict__ b, float* __restrict__ out,
                     __half* __restrict__ outh)
{
    const long row = blockIdx.x;
    const int tid = threadIdx.x;
    float4 v = ((const float4*)(x + row * 512))[tid];
    float s = v.x + v.y + v.z + v.w;
    __shared__ float sh[4];
#pragma unroll
    for (int o = 16; o; o >>= 1) s += __shfl_xor_sync(0xffffffffu, s, o);
    if ((tid & 31) == 0) sh[tid >> 5] = s;
    __syncthreads();
    const float mu = (sh[0] + sh[1] + sh[2] + sh[3]) * (1.f / 512.f);
    float dx = v.x - mu, dy = v.y - mu, dz = v.z - mu, dw = v.w - mu;
    float s2 = dx * dx + dy * dy + dz * dz + dw * dw;
    __syncthreads();
#pragma unroll
    for (int o = 16; o; o >>= 1) s2 += __shfl_xor_sync(0xffffffffu, s2, o);
    if ((tid & 31) == 0) sh[tid >> 5] = s2;
    __syncthreads();
    const float rs = rsqrtf((sh[0] + sh[1] + sh[2] + sh[3]) * (1.f / 512.f) + 1e-5f);
    const float4 gg = ((const float4*)g)[tid];
    const float4 bb = ((const float4*)b)[tid];
    float4 r;
    r.x = dx * rs * gg.x + bb.x;
    r.y = dy * rs * gg.y + bb.y;
    r.z = dz * rs * gg.z + bb.z;
    r.w = dw * rs * gg.w + bb.w;
    if (out) ((float4*)(out + row * 512))[tid] = r;
    __half2* oh = (__half2*)(outh + row * 512) + 2 * tid;
    oh[0] = __floats2half2_rn(r.x, r.y);
    oh[1] = __floats2half2_rn(r.z, r.w);
}

// ------ softmax L=1152: 2 rows per 256-thread CTA (independent groups) ------
__global__ void __launch_bounds__(256)
softmax1152_k(__half* __restrict__ P, float scale, float* __restrict__ subsum)
{
    const int tid = threadIdx.x;
    const int grp = tid >> 7, t = tid & 127;
    const long row = (long)blockIdx.x * 2 + grp;
    __half* pr = P + row * 1152L;
    const int lane = t & 31, wid = t >> 5;
    const bool tail = t < 64;

    uint4 u = ((const uint4*)pr)[t];
    __half2* hp = (__half2*)&u;
    float v[10];
#pragma unroll
    for (int j = 0; j < 4; j++) {
        float2 f = __half22float2(hp[j]);
        v[2 * j] = f.x * scale; v[2 * j + 1] = f.y * scale;
    }
    v[8] = v[9] = -3.0e38f;
    if (tail) {
        float2 f = __half22float2(((const __half2*)pr)[512 + t]);
        v[8] = f.x * scale; v[9] = f.y * scale;
    }

    float mx = v[0];
#pragma unroll
    for (int j = 1; j < 10; j++) mx = fmaxf(mx, v[j]);
    __shared__ float sh[2][4];
#pragma unroll
    for (int o = 16; o; o >>= 1) mx = fmaxf(mx, __shfl_xor_sync(0xffffffffu, mx, o));
    if (lane == 0) sh[grp][wid] = mx;
    __syncthreads();
    const float bm = fmaxf(fmaxf(sh[grp][0], sh[grp][1]), fmaxf(sh[grp][2], sh[grp][3]));

    float s = 0.f;
#pragma unroll
    for (int j = 0; j < 10; j++) { float e = __expf(v[j] - bm); v[j] = e; s += e; }
    float ssub = 0.f;
    if (t >= 16 && t < 80) {
#pragma unroll
        for (int j = 0; j < 8; j++) ssub += v[j];
    }
    __syncthreads();
#pragma unroll
    for (int o = 16; o; o >>= 1) s += __shfl_xor_sync(0xffffffffu, s, o);
    if (lane == 0) sh[grp][wid] = s;
    __syncthreads();
    const float tot = sh[grp][0] + sh[grp][1] + sh[grp][2] + sh[grp][3];
    const float inv = 1.f / tot;

    __syncthreads();
#pragma unroll
    for (int o = 16; o; o >>= 1) ssub += __shfl_xor_sync(0xffffffffu, ssub, o);
    if (lane == 0) sh[grp][wid] = ssub;
    __syncthreads();
    if (t == 0 && subsum)
        subsum[row] = (sh[grp][0] + sh[grp][1] + sh[grp][2] + sh[grp][3]) * inv;

#pragma unroll
    for (int j = 0; j < 4; j++)
        hp[j] = __floats2half2_rn(v[2 * j] * inv, v[2 * j + 1] * inv);
    ((uint4*)pr)[t] = u;
    if (tail)
        ((__half2*)pr)[512 + t] = __floats2half2_rn(v[8] * inv, v[9] * inv);
}

// -------------------- warp-per-row softmax L=128 ----------------------------
__global__ void __launch_bounds__(256)
softmax128w_k(__half* __restrict__ P, float scale)
{
    const long row = (long)blockIdx.x * 8 + (threadIdx.x >> 5);
    const int lane = threadIdx.x & 31;
    __half* pr = P + row * 128L;
    uint2 u = ((const uint2*)pr)[lane];
    __half2* hp = (__half2*)&u;
    float2 f0 = __half22float2(hp[0]), f1 = __half22float2(hp[1]);
    float v0 = f0.x * scale, v1 = f0.y * scale, v2 = f1.x * scale, v3 = f1.y * scale;
    float mx = fmaxf(fmaxf(v0, v1), fmaxf(v2, v3));
#pragma unroll
    for (int o = 16; o; o >>= 1) mx = fmaxf(mx, __shfl_xor_sync(0xffffffffu, mx, o));
    float e0 = __expf(v0 - mx), e1 = __expf(v1 - mx);
    float e2 = __expf(v2 - mx), e3 = __expf(v3 - mx);
    float s = e0 + e1 + e2 + e3;
#pragma unroll
    for (int o = 16; o; o >>= 1) s += __shfl_xor_sync(0xffffffffu, s, o);
    const float inv = 1.f / s;
    hp[0] = __floats2half2_rn(e0 * inv, e1 * inv);
    hp[1] = __floats2half2_rn(e2 * inv, e3 * inv);
    ((uint2*)pr)[lane] = u;
}

// -------------------- embed / mse / attnsum / init / final ------------------
__global__ void embed_k(const int* __restrict__ seq, const float* __restrict__ emb,
                        float* __restrict__ x)
{
    long i = (long)blockIdx.x * blockDim.x + threadIdx.x;
    if (i >= 2097152L) return;
    int d = (int)(i & 511);
    long bt = i >> 9;
    int t = (int)(bt & 511);
    int tok = seq[bt];
    int j2 = d & ~1;
    float ang = (float)t * expf(-0.017988946039015984f * (float)j2);
    float pe = (d & 1) ? cosf(ang) : sinf(ang);
    x[i] = emb[(long)tok * 512 + d] + pe;
}

__global__ void mse_k(const float* __restrict__ a, const float* __restrict__ b,
                      const float* __restrict__ S, float* __restrict__ outScalar, long n)
{
    long i0 = (long)blockIdx.x * blockDim.x + threadIdx.x;
    long stride = (long)gridDim.x * blockDim.x;
    float s = 0.f;
    for (long i = i0; i < n; i += stride) {
        float d = a[i] / S[i >> 6] - b[i];
        s += d * d;
    }
    __shared__ float sh[8];
#pragma unroll
    for (int o = 16; o; o >>= 1) s += __shfl_xor_sync(0xffffffffu, s, o);
    int tid = threadIdx.x;
    if ((tid & 31) == 0) sh[tid >> 5] = s;
    __syncthreads();
    if (tid == 0) {
        float tot = 0.f;
#pragma unroll
        for (int w = 0; w < 8; w++) tot += sh[w];
        atomicAdd(outScalar, tot);
    }
}

// attns_mean: 4-way split over slices (64 each), atomic accumulation
__global__ void attnsum_k(const __half* __restrict__ dotsH, float* __restrict__ out)
{
    const int part = blockIdx.x / 288;
    long i = (long)(blockIdx.x % 288) * 256 + threadIdx.x;   // uint4 idx < 73728
    const uint4* p = (const uint4*)dotsH + i + (long)part * 64 * 73728L;
    float s[8];
#pragma unroll
    for (int j = 0; j < 8; j++) s[j] = 0.f;
#pragma unroll 4
    for (int sl = 0; sl < 64; sl++) {
        uint4 u = p[(long)sl * 73728L];
        const __half2* hp = (const __half2*)&u;
#pragma unroll
        for (int j = 0; j < 4; j++) {
            float2 f = __half22float2(hp[j]);
            s[2 * j] += f.x; s[2 * j + 1] += f.y;
        }
    }
    float* o = out + OFF_ATTN + 8 * i;
#pragma unroll
    for (int j = 0; j < 8; j++) atomicAdd(o + j, s[j] * (1.f / 256.f));
}

__global__ void init_k(float* __restrict__ out)
{
    long i = (long)blockIdx.x * 256 + threadIdx.x;
    if (i < 294912L) ((float2*)(out + OFF_ATTN))[i] = make_float2(0.f, 0.f);
    if (i == 0) { out[OFF_AUX] = 0.f; out[OFF_ZERO] = 0.f; }
}
__global__ void final_k(float* __restrict__ out)
{
    if (threadIdx.x == 0) out[OFF_AUX] *= (1.f / (4.f * 2097152.f));
}

// ---------------------------------------------------------------------------
extern "C" void kernel_launch(void* const* d_in, const int* in_sizes, int n_in,
                              void* d_out, int out_size)
{
    const int*   seq   = (const int*)  d_in[0];
    const float* mems  = (const float*)d_in[2];
    const float* cmems = (const float*)d_in[3];
    const float* emb   = (const float*)d_in[4];
    const float* ln1g  = (const float*)d_in[5];
    const float* ln1b  = (const float*)d_in[6];
    const float* Wq    = (const float*)d_in[7];
    const float* Wkv   = (const float*)d_in[8];
    const float* Wo    = (const float*)d_in[9];
    const float* bo    = (const float*)d_in[10];
    const float* convw = (const float*)d_in[11];
    const float* convb = (const float*)d_in[12];
    const float* ln2g  = (const float*)d_in[13];
    const float* ln2b  = (const float*)d_in[14];
    const float* W1    = (const float*)d_in[15];
    const float* b1    = (const float*)d_in[16];
    const float* W2    = (const float*)d_in[17];
    const float* b2    = (const float*)d_in[18];
    float* out = (float*)d_out;

    __half *hmems, *hcmems, *hxn, *hxn2, *qh, *kvh, *ckvh, *dotsH, *dots2H;
    __half *attnoh, *ffhh, *cmh;
    __half *wqkv16, *hWo, *cwh, *hW1, *hW2;
    float *o1, *o2, *Ssub;
    cudaGetSymbolAddress((void**)&hmems, g_hmems);   cudaGetSymbolAddress((void**)&hcmems, g_hcmems);
    cudaGetSymbolAddress((void**)&hxn, g_hxn);       cudaGetSymbolAddress((void**)&hxn2, g_hxn2);
    cudaGetSymbolAddress((void**)&qh, g_qh);         cudaGetSymbolAddress((void**)&kvh, g_kvh);
    cudaGetSymbolAddress((void**)&ckvh, g_ckvh);     cudaGetSymbolAddress((void**)&dotsH, g_dotsH);
    cudaGetSymbolAddress((void**)&dots2H, g_dots2H); cudaGetSymbolAddress((void**)&attnoh, g_attnoh);
    cudaGetSymbolAddress((void**)&ffhh, g_ffhh);     cudaGetSymbolAddress((void**)&cmh, g_cmh);
    cudaGetSymbolAddress((void**)&wqkv16, g_wqkv16); cudaGetSymbolAddress((void**)&hWo, g_hWo);
    cudaGetSymbolAddress((void**)&cwh, g_cwh);       cudaGetSymbolAddress((void**)&hW1, g_hW1);
    cudaGetSymbolAddress((void**)&hW2, g_hW2);
    cudaGetSymbolAddress((void**)&o1, g_o1);         cudaGetSymbolAddress((void**)&o2, g_o2);
    cudaGetSymbolAddress((void**)&Ssub, g_S);

    const int SM128  = 3 * (128 + 128) * 80;               // 61440
    const int SM128T = 3 * (128 * 80 + 32 * 272);          // 56832
    const int SM64T  = 3 * (128 * 80 + 32 * 144);          // 44544
    cudaFuncSetAttribute(hm_gemm<128,0,1,false,false>, cudaFuncAttributeMaxDynamicSharedMemorySize, SM128);
    cudaFuncSetAttribute(hm_gemm<128,1,2,false,false>, cudaFuncAttributeMaxDynamicSharedMemorySize, SM128);
    cudaFuncSetAttribute(hm_gemm<128,0,1,true,false>,  cudaFuncAttributeMaxDynamicSharedMemorySize, SM128T);
    cudaFuncSetAttribute(hm_gemm<128,2,0,true,false>,  cudaFuncAttributeMaxDynamicSharedMemorySize, SM128T);
    cudaFuncSetAttribute(hm_gemm<128,3,1,true,false>,  cudaFuncAttributeMaxDynamicSharedMemorySize, SM128T);
    cudaFuncSetAttribute(hm_gemm<128,0,3,true,false>,  cudaFuncAttributeMaxDynamicSharedMemorySize, SM128T);
    cudaFuncSetAttribute(hm_gemm<64,0,1,true,true>,    cudaFuncAttributeMaxDynamicSharedMemorySize, SM64T);
    cudaFuncSetAttribute(hm_gemm<64,0,0,true,false>,   cudaFuncAttributeMaxDynamicSharedMemorySize, SM64T);

    float* x   = out;
    float* aux = out + OFF_AUX;

    init_k <<<1152, 256>>>(out);
    embed_k<<<8192, 256>>>(seq, emb, x);

    // ---- one-time conversions (no transposes) ----
    cvtpad_k<<<1024, 256>>>(Wq,  wqkv16,       128, 512, 1536, 786432, 262144L);
    cvtpad_k<<<2048, 256>>>(Wkv, wqkv16 + 512, 256, 512, 1536, 786432, 524288L);
    cvt16_k<<<1024, 256>>>(Wo, hWo, 262144L);
    cvt16_k<<<4096, 256>>>(W1, hW1, 1048576L);
    cvt16_k<<<4096, 256>>>(W2, hW2, 1048576L);
    convt2_k<<<16384, 256>>>(convw, cwh);
    cvt16_k<<<8192, 256>>>(mems,  hmems,  2097152L);
    cvt16_k<<<2048, 256>>>(cmems, hcmems, 524288L);

    const __half* Wkv16 = wqkv16 + 512;

    // ---- hoisted layer-input GEMMs (z = l*8+b) ----
    hm_gemm<128,0,1,true,false><<<dim3(8,1,32),256,SM128T>>>(hcmems, Wkv16, nullptr, kvh,
        512, 512,1536,1024, 524288,65536,0, 786432,0,0, 9437184,1179648,0, 8,1, nullptr,0,0,0);
    hm_gemm<128,0,1,true,false><<<dim3(8,4,32),256,SM128T>>>(hmems, Wkv16, nullptr, kvh + 131072,
        512, 512,1536,1024, 2097152,262144,0, 786432,0,0, 9437184,1179648,0, 8,1, nullptr,0,0,0);
    hm_gemm<128,1,2,false,false><<<dim3(4,8,4),256,SM128>>>(hmems, cwh, out + OFF_CMEMS, cmh,
        2048, 2048,2048,512, 2097152,0,0, 1048576,0,0, 524288,0,0, 1,1, convb,512,0,0);
    hm_gemm<128,0,1,true,false><<<dim3(8,1,32),256,SM128T>>>(cmh, Wkv16, nullptr, ckvh,
        512, 512,1536,1024, 524288,65536,0, 786432,0,0, 1048576,131072,0, 8,1, nullptr,0,0,0);

    for (int i = 0; i < 4; i++) {
        const __half* wqkv16_i = wqkv16 + (long)i * 786432;
        const __half* hWo_i    = hWo    + (long)i * 262144;
        const __half* hW1_i    = hW1    + (long)i * 1048576;
        const __half* hW2_i    = hW2    + (long)i * 1048576;
        __half* qh_l    = qh    + (long)i * 2097152;
        __half* kvh_l   = kvh   + (long)i * 9437184;
        __half* dotsH_l = dotsH + (long)i * 37748736;
        float*  o1_l    = o1    + (long)i * 2097152;
        float*  Ssub_l  = Ssub  + (long)i * 32768;
        float*  xn = out + OFF_MEMS + (long)i * 2097152;

        ln_k<<<4096, 128>>>(x, ln1g + i * 512, ln1b + i * 512, xn, hxn);

        hm_gemm<128,0,3,true,false><<<dim3(12,4,8),256,SM128T>>>(hxn, wqkv16_i,
            (float*)(kvh_l + 655360), qh_l,
            512, 512,1536,512, 262144,0,0, 0,0,0, 262144,0,1179648, 1,1, nullptr,0,0,0);

        hm_gemm<128,0,1,false,false><<<dim3(9,4,64),256,SM128>>>(qh_l, kvh_l, nullptr, dotsH_l,
            64, 512,1024,1152, 262144,64,0, 1179648,64,0, 4718592,589824,0, 8,1, nullptr,0,0,0);

        softmax1152_k<<<16384,256>>>(dotsH_l, 0.125f, Ssub_l);

        hm_gemm<64,0,1,true,true><<<dim3(1,4,64),256,SM64T>>>(dotsH_l, kvh_l + 512, o1_l, attnoh,
            1152, 1152,1024,512, 4718592,589824,0, 1179648,64,0, 262144,64,0, 8,1,
            nullptr,0, 262144,32768);

        hm_gemm<128,2,0,true,false><<<dim3(4,32,1),256,SM128T>>>(attnoh, hWo_i, x, nullptr,
            512, 512,512,512, 0,0,0, 0,0,0, 0,0,0, 1,1, bo + i * 512, 0,0,0);

        ln_k<<<4096,128>>>(x, ln2g + i * 512, ln2b + i * 512, nullptr, hxn2);
        hm_gemm<128,3,1,true,false><<<dim3(16,32,1),256,SM128T>>>(hxn2, hW1_i, nullptr, ffhh,
            512, 512,2048,2048, 0,0,0, 0,0,0, 0,0,0, 1,1, b1 + i * 2048, 0,0,0);
        hm_gemm<128,2,0,true,false><<<dim3(4,32,1),256,SM128T>>>(ffhh, hW2_i, x, nullptr,
            2048, 2048,512,512, 0,0,0, 0,0,0, 0,0,0, 1,1, b2 + i * 512, 0,0,0);
    }

    // ---- deferred aux-cmem chain ----
    hm_gemm<128,0,1,false,false><<<dim3(1,4,256),256,SM128>>>(qh, ckvh, nullptr, dots2H,
        64, 512,1024,128, 2097152,262144,64, 1048576,131072,64,
        4194304,524288,65536, 8,8, nullptr,0,0,0);
    softmax128w_k<<<16384,256>>>(dots2H, 0.125f);
    hm_gemm<64,0,0,true,false><<<dim3(1,4,256),256,SM64T>>>(dots2H, ckvh + 512, o2, nullptr,
        128, 128,1024,64, 4194304,524288,65536, 1048576,131072,64,
        2097152,262144,32768, 8,8, nullptr,0,0,0);
    mse_k<<<2048,256>>>(o1, o2, Ssub, aux, 8388608L);

    attnsum_k<<<1152,256>>>(dotsH, out);
    final_k<<<1,32>>>(out);
}